// round 6
// baseline (speedup 1.0000x reference)
#include <cuda_runtime.h>

#define N_ELEC 62
#define IN_CH  5
#define HID    32
#define N_CLS  3
#define SPITCH 64          // padded row stride for S / A
#define GPB    8           // graphs per block (4 f32x2 pairs)
#define NPAIR  (GPB/2)
#define NTHR   1024
#define NQ     4           // i-loop quarters

// Precomputed S = M^2, M = D^{-1/2} A D^{-1/2}; padded [62][64], cols 62..63 = 0
__device__ float g_S[N_ELEC * SPITCH];

#define FMA2(acc, a, b) \
    asm("fma.rn.f32x2 %0, %1, %2, %0;" : "+l"(acc) : "l"(a), "l"(b))
#define ADD2(acc, v) \
    asm("add.rn.f32x2 %0, %0, %1;" : "+l"(acc) : "l"(v))
#define PACK2(d, s) \
    asm("mov.b64 %0, {%1, %1};" : "=l"(d) : "f"(s))
#define UNPK2(lo, hi, v) \
    asm("mov.b64 {%0, %1}, %2;" : "=f"(lo), "=f"(hi) : "l"(v))

// ---------------------------------------------------------------------------
// Setup: grid = 62 blocks, block i computes row i of S = M @ M.
// ---------------------------------------------------------------------------
__global__ __launch_bounds__(128) void rgnn_setup_kernel(
    const float* __restrict__ adj_tril)
{
    __shared__ float A[N_ELEC * SPITCH];
    __shared__ float dinv[N_ELEC];
    __shared__ float t[N_ELEC];
    const int tid = threadIdx.x;
    const int i   = blockIdx.x;

    for (int idx = tid; idx < N_ELEC * N_ELEC; idx += 128) {
        int r = idx / N_ELEC, c = idx % N_ELEC;
        int a = r > c ? r : c;
        int b = r > c ? c : r;
        A[r * SPITCH + c] = adj_tril[a * (a + 1) / 2 + b];
    }
    __syncthreads();

    if (tid < N_ELEC) {
        float d = 0.f;
        #pragma unroll 2
        for (int c = 0; c < N_ELEC; c++) d += fabsf(A[tid * SPITCH + c]);
        dinv[tid] = (d > 0.f) ? rsqrtf(d) : 0.f;
    }
    __syncthreads();

    if (tid < N_ELEC) {
        float dk = dinv[tid];
        t[tid] = dinv[i] * dk * dk * A[i * SPITCH + tid];
    }
    __syncthreads();

    if (tid < SPITCH) {
        const int j = tid;
        float s = 0.f;
        if (j < N_ELEC) {
            #pragma unroll 2
            for (int k = 0; k < N_ELEC; k++)
                s = fmaf(t[k], A[k * SPITCH + j], s);
            s *= dinv[j];
        }
        g_S[i * SPITCH + j] = s;         // pad cols 62..63 get 0
    }
}

// ---------------------------------------------------------------------------
// Main: phase A = pair-packed propagation over 4 i-quarters (short chains,
// 32 warps/block -> 64 warps/SM); phase B = 4 warps per graph.
// ---------------------------------------------------------------------------
__global__ __launch_bounds__(NTHR) void rgnn_main_kernel(
    const float* __restrict__ x, const float* __restrict__ lin_w,
    const float* __restrict__ lin_b, const float* __restrict__ fc_w,
    const float* __restrict__ fc_b, float* __restrict__ out, int B)
{
    // phase A: Ssh [62*64] (15872B) | Xp [NPAIR][62][6] float2 (11904B)
    // phase B: Ysh [GPB][5][64] (10240B) aliases the Ssh region
    __shared__ __align__(16) float smem[N_ELEC * SPITCH + NPAIR * N_ELEC * 6 * 2];
    float*  Ssh = smem;
    float2* Xp  = (float2*)(smem + N_ELEC * SPITCH);
    float*  Ysh = smem;
    __shared__ __align__(16) unsigned long long scr[(NQ-1) * NPAIR * IN_CH * 64]; // 30720B
    __shared__ float Wsh[HID][IN_CH];
    __shared__ float bsh[HID];
    __shared__ float Fsh[N_CLS][HID];
    __shared__ float fcb[N_CLS];
    __shared__ float red[GPB][NQ][N_CLS];

    const int tid = threadIdx.x;
    const int g0  = blockIdx.x * GPB;

    // ---- stage S (float4), small weights, X (pair-interleaved) ----
    {
        const float4* gs4 = (const float4*)g_S;
        float4* ss4 = (float4*)Ssh;
        for (int idx = tid; idx < N_ELEC * SPITCH / 4; idx += NTHR)
            ss4[idx] = gs4[idx];
    }
    if (tid < HID * IN_CH + HID + N_CLS * HID + N_CLS) {
        const int idx = tid;
        if (idx < 160)      ((float*)Wsh)[idx] = lin_w[idx];
        else if (idx < 192) bsh[idx - 160] = lin_b[idx - 160];
        else if (idx < 288) ((float*)Fsh)[idx - 192] = fc_w[idx - 192];
        else                fcb[idx - 288] = fc_b[idx - 288];
    }
    {
        const float* xg = x + (size_t)g0 * N_ELEC * IN_CH;
        const int nv = (B - g0) < GPB ? (B - g0) : GPB;
        const int total = nv * N_ELEC * IN_CH;
        for (int idx = tid; idx < total; idx += NTHR) {
            int g = idx / (N_ELEC * IN_CH);
            int r = idx % (N_ELEC * IN_CH);
            int i = r / IN_CH, c = r % IN_CH;
            ((float*)&Xp[((g >> 1) * N_ELEC + i) * 6 + c])[g & 1] = xg[idx];
        }
    }
    __syncthreads();

    // ---- phase A: y_j = sum_i S[i][j] * x_i ; thread = (q, pair, j) ----
    const int j = tid & 63;
    const int p = (tid >> 6) & 3;        // pair -> graphs 2p, 2p+1
    const int q = tid >> 8;              // i-quarter 0..3
    // quarters: 16,16,15,15  ->  [0,16) [16,32) [32,47) [47,62)
    const int ibeg = (q < 2) ? q * 16 : 32 + (q - 2) * 15;
    const int icnt = (q < 2) ? 16 : 15;
    unsigned long long a0=0,a1=0,a2=0,a3=0,a4=0;

    if (j < N_ELEC) {
        const unsigned xb = (unsigned)__cvta_generic_to_shared(&Xp[p * N_ELEC * 6]);
        #pragma unroll 4
        for (int ii = 0; ii < icnt; ii++) {
            const int i = ibeg + ii;
            float s = Ssh[i * SPITCH + j];             // stride-1, conflict-free
            unsigned long long s2; PACK2(s2, s);
            unsigned long long q0,q1,q2,q3,q4;
            unsigned a = xb + i * 48;                  // broadcast
            asm("ld.shared.v2.u64 {%0,%1}, [%2];"    : "=l"(q0), "=l"(q1) : "r"(a));
            asm("ld.shared.v2.u64 {%0,%1}, [%2+16];" : "=l"(q2), "=l"(q3) : "r"(a));
            asm("ld.shared.u64 %0, [%1+32];"         : "=l"(q4)           : "r"(a));
            FMA2(a0,s2,q0); FMA2(a1,s2,q1); FMA2(a2,s2,q2); FMA2(a3,s2,q3); FMA2(a4,s2,q4);
        }
    }

    // combine quarters: q=1..3 store partials (layout [q-1][p][c][j])
    if (q > 0) {
        unsigned long long* sp = &scr[((q - 1) * NPAIR + p) * IN_CH * 64 + j];
        sp[0]   = a0;  sp[64]  = a1;  sp[128] = a2;  sp[192] = a3;  sp[256] = a4;
    }
    __syncthreads();   // also retires all Ssh/Xp reads -> region reusable

    if (q == 0) {
        #pragma unroll
        for (int qq = 0; qq < NQ - 1; qq++) {
            const unsigned long long* sp = &scr[(qq * NPAIR + p) * IN_CH * 64 + j];
            ADD2(a0, sp[0]);   ADD2(a1, sp[64]);  ADD2(a2, sp[128]);
            ADD2(a3, sp[192]); ADD2(a4, sp[256]);
        }
        float lo, hi;
        if (j < N_ELEC) {
            #define YW(acc, c) \
                UNPK2(lo, hi, acc); \
                Ysh[(2*p)   * 320 + (c) * 64 + j] = lo; \
                Ysh[(2*p+1) * 320 + (c) * 64 + j] = hi;
            YW(a0, 0) YW(a1, 1) YW(a2, 2) YW(a3, 3) YW(a4, 4)
            #undef YW
        } else {
            #pragma unroll
            for (int c = 0; c < IN_CH; c++) {          // zero pads j = 62, 63
                Ysh[(2*p)   * 320 + c * 64 + j] = 0.f;
                Ysh[(2*p+1) * 320 + c * 64 + j] = 0.f;
            }
        }
    }
    __syncthreads();

    // ---- phase B: 4 warps per graph, lane = hidden unit o ----
    const int o    = tid & 31;
    const int warp = tid >> 5;           // 0..31
    const int g    = warp >> 2;          // 0..7
    const int qt   = warp & 3;           // j quarter (16 j's = 8 pairs)
    const float w0 = Wsh[o][0], w1 = Wsh[o][1], w2 = Wsh[o][2],
                w3 = Wsh[o][3], w4 = Wsh[o][4];
    unsigned long long wd0,wd1,wd2,wd3,wd4,bd;
    PACK2(wd0,w0); PACK2(wd1,w1); PACK2(wd2,w2); PACK2(wd3,w3); PACK2(wd4,w4);
    PACK2(bd, bsh[o]);
    const float f0 = Fsh[0][o], f1 = Fsh[1][o], f2 = Fsh[2][o];

    {
        const unsigned yb = (unsigned)__cvta_generic_to_shared(&Ysh[g * 320])
                            + qt * 64;                 // j offset 16 per quarter
        float ph = 0.f;
        #pragma unroll
        for (int k = 0; k < 8; k++) {                  // 8 j-pairs per warp
            unsigned long long y0,y1,y2,y3,y4;
            unsigned a = yb + k * 8;
            asm("ld.shared.u64 %0, [%1];"      : "=l"(y0) : "r"(a));
            asm("ld.shared.u64 %0, [%1+256];"  : "=l"(y1) : "r"(a));
            asm("ld.shared.u64 %0, [%1+512];"  : "=l"(y2) : "r"(a));
            asm("ld.shared.u64 %0, [%1+768];"  : "=l"(y3) : "r"(a));
            asm("ld.shared.u64 %0, [%1+1024];" : "=l"(y4) : "r"(a));
            unsigned long long v = bd;
            FMA2(v, wd0, y0); FMA2(v, wd1, y1); FMA2(v, wd2, y2);
            FMA2(v, wd3, y3); FMA2(v, wd4, y4);
            float lo, hi; UNPK2(lo, hi, v);
            ph += fmaxf(lo, 0.f);
            ph += fmaxf(hi, 0.f);
        }
        float s0 = f0 * ph, s1 = f1 * ph, s2 = f2 * ph;
        #pragma unroll
        for (int off = 16; off > 0; off >>= 1) {
            s0 += __shfl_down_sync(0xffffffffu, s0, off);
            s1 += __shfl_down_sync(0xffffffffu, s1, off);
            s2 += __shfl_down_sync(0xffffffffu, s2, off);
        }
        if (o == 0) {
            red[g][qt][0] = s0;
            red[g][qt][1] = s1;
            red[g][qt][2] = s2;
        }
    }
    __syncthreads();

    if (tid < GPB * N_CLS) {
        const int gg = tid / N_CLS, c = tid % N_CLS;
        if (g0 + gg < B)
            out[(size_t)(g0 + gg) * N_CLS + c] =
                red[gg][0][c] + red[gg][1][c] + red[gg][2][c] + red[gg][3][c]
                + fcb[c];
    }
}

// ---------------------------------------------------------------------------
extern "C" void kernel_launch(void* const* d_in, const int* in_sizes, int n_in,
                              void* d_out, int out_size) {
    const float* x        = (const float*)d_in[0];
    const float* adj_tril = (const float*)d_in[1];
    const float* lin_w    = (const float*)d_in[2];
    const float* lin_b    = (const float*)d_in[3];
    const float* fc_w     = (const float*)d_in[4];
    const float* fc_b     = (const float*)d_in[5];
    // d_in[6] edge_index / d_in[7] batch_idx are structurally redundant.

    const int B = in_sizes[0] / (N_ELEC * IN_CH);

    rgnn_setup_kernel<<<N_ELEC, 128>>>(adj_tril);

    const int grid = (B + GPB - 1) / GPB;
    rgnn_main_kernel<<<grid, NTHR>>>(x, lin_w, lin_b, fc_w, fc_b,
                                     (float*)d_out, B);
}

// round 7
// speedup vs baseline: 1.1667x; 1.1667x over previous
#include <cuda_runtime.h>

#define N_ELEC 62
#define IN_CH  5
#define HID    32
#define N_CLS  3
#define GPB    8           // graphs per block (4 f32x2 pairs)
#define NTHR   512

// S = M^2 stored PAIR-INTERLEAVED: g_S[i*64 + 2*l + h] = S[i][l + 32*h]
__device__ float g_S[N_ELEC * 64];

typedef unsigned long long u64;

#define FMA2(acc, a, b) \
    asm("fma.rn.f32x2 %0, %1, %2, %0;" : "+l"(acc) : "l"(a), "l"(b))
#define ADD2(acc, v) \
    asm("add.rn.f32x2 %0, %0, %1;" : "+l"(acc) : "l"(v))
#define PACK2(d, s) \
    asm("mov.b64 %0, {%1, %1};" : "=l"(d) : "f"(s))
#define UNPK2(lo, hi, v) \
    asm("mov.b64 {%0, %1}, %2;" : "=f"(lo), "=f"(hi) : "l"(v))

// ---------------------------------------------------------------------------
// Setup: grid = 62 blocks, block i computes row i of S = M @ M, interleaved.
// ---------------------------------------------------------------------------
__global__ __launch_bounds__(128) void rgnn_setup_kernel(
    const float* __restrict__ adj_tril)
{
    __shared__ float A[N_ELEC * 64];
    __shared__ float dinv[N_ELEC];
    __shared__ float t[N_ELEC];
    const int tid = threadIdx.x;
    const int i   = blockIdx.x;

    for (int idx = tid; idx < N_ELEC * N_ELEC; idx += 128) {
        int r = idx / N_ELEC, c = idx % N_ELEC;
        int a = r > c ? r : c;
        int b = r > c ? c : r;
        A[r * 64 + c] = adj_tril[a * (a + 1) / 2 + b];
    }
    __syncthreads();

    if (tid < N_ELEC) {
        float d = 0.f;
        #pragma unroll 2
        for (int c = 0; c < N_ELEC; c++) d += fabsf(A[tid * 64 + c]);
        dinv[tid] = (d > 0.f) ? rsqrtf(d) : 0.f;
    }
    __syncthreads();

    if (tid < N_ELEC) {
        float dk = dinv[tid];
        t[tid] = dinv[i] * dk * dk * A[i * 64 + tid];
    }
    __syncthreads();

    if (tid < 64) {
        const int j = tid;
        float s = 0.f;
        if (j < N_ELEC) {
            #pragma unroll 2
            for (int k = 0; k < N_ELEC; k++)
                s = fmaf(t[k], A[k * 64 + j], s);
            s *= dinv[j];
        }
        // pair-interleaved write: slot = 2*(j&31) + (j>>5); pads j=62,63 -> 0
        g_S[i * 64 + ((j & 31) << 1) + (j >> 5)] = s;
    }
}

// ---------------------------------------------------------------------------
// Main kernel. Thread = 2 j's (l, l+32) x 1 pair; warp = (pair, i-quarter).
// ---------------------------------------------------------------------------
__global__ __launch_bounds__(NTHR, 3) void rgnn_main_kernel(
    const float* __restrict__ x, const float* __restrict__ lin_w,
    const float* __restrict__ lin_b, const float* __restrict__ fc_w,
    const float* __restrict__ fc_b, float* __restrict__ out, int B)
{
    // Union (30720 B):
    //  phase A : Spk [62*64]f @0 (15872B) | Xp [4][62][6]u64 @15872 (11904B)
    //  reduce  : set0 @10240 (10240B) | set1 @20480 (10240B)
    //  phase B : Ysh [8][5][64]f @0 (10240B)
    __shared__ __align__(16) float uni[7680];
    float* Spk  = uni;
    u64*   Xp   = (u64*)(uni + 3968);
    float* Ysh  = uni;
    u64*   set0 = (u64*)(uni + 2560);
    u64*   set1 = (u64*)(uni + 5120);
    __shared__ float Wsh[HID][IN_CH];
    __shared__ float bsh[HID];
    __shared__ float Fsh[N_CLS][HID];
    __shared__ float fcb[N_CLS];
    __shared__ float red[GPB][2][N_CLS];

    const int tid = threadIdx.x;
    const int g0  = blockIdx.x * GPB;

    // ---- stage S (float4), small weights, X (pair-interleaved) ----
    {
        const float4* gs4 = (const float4*)g_S;
        float4* ss4 = (float4*)Spk;
        for (int idx = tid; idx < N_ELEC * 64 / 4; idx += NTHR)
            ss4[idx] = gs4[idx];
    }
    if (tid < HID * IN_CH + HID + N_CLS * HID + N_CLS) {
        const int idx = tid;
        if (idx < 160)      ((float*)Wsh)[idx] = lin_w[idx];
        else if (idx < 192) bsh[idx - 160] = lin_b[idx - 160];
        else if (idx < 288) ((float*)Fsh)[idx - 192] = fc_w[idx - 192];
        else                fcb[idx - 288] = fc_b[idx - 288];
    }
    {
        const float* xg = x + (size_t)g0 * N_ELEC * IN_CH;
        const int nv = (B - g0) < GPB ? (B - g0) : GPB;
        const int total = nv * N_ELEC * IN_CH;
        for (int idx = tid; idx < total; idx += NTHR) {
            int g = idx / (N_ELEC * IN_CH);
            int r = idx % (N_ELEC * IN_CH);
            int i = r / IN_CH, c = r % IN_CH;
            ((float*)&Xp[((g >> 1) * N_ELEC + i) * 6 + c])[g & 1] = xg[idx];
        }
    }
    __syncthreads();

    // ---- phase A: warp = (pair, quarter); thread covers j = l and l+32 ----
    const int l = tid & 31;
    const int w = tid >> 5;              // 0..15
    const int p = w & 3;                 // pair -> graphs 2p, 2p+1
    const int q = w >> 2;                // i-quarter 0..3
    // quarters: 16,16,15,15 -> [0,16) [16,32) [32,47) [47,62)
    const int ibeg = (q < 2) ? q * 16 : 32 + (q - 2) * 15;
    const int icnt = (q < 2) ? 16 : 15;

    u64 A0[IN_CH], A1[IN_CH];            // acc for j=l (A0) and j=l+32 (A1)
    #pragma unroll
    for (int c = 0; c < IN_CH; c++) { A0[c] = 0ull; A1[c] = 0ull; }

    {
        const unsigned sb = (unsigned)__cvta_generic_to_shared(Spk) + l * 8;
        const unsigned xb = (unsigned)__cvta_generic_to_shared(&Xp[p * N_ELEC * 6]);
        #pragma unroll 4
        for (int ii = 0; ii < icnt; ii++) {
            const int i = ibeg + ii;
            u64 spk;
            asm("ld.shared.u64 %0, [%1];" : "=l"(spk) : "r"(sb + i * 256));
            float slo, shi; UNPK2(slo, shi, spk);
            u64 s0, s1; PACK2(s0, slo); PACK2(s1, shi);
            u64 x0,x1,x2,x3,x4;
            const unsigned a = xb + i * 48;
            asm("ld.shared.v2.u64 {%0,%1}, [%2];"    : "=l"(x0), "=l"(x1) : "r"(a));
            asm("ld.shared.v2.u64 {%0,%1}, [%2+16];" : "=l"(x2), "=l"(x3) : "r"(a));
            asm("ld.shared.u64 %0, [%1+32];"         : "=l"(x4)           : "r"(a));
            FMA2(A0[0],s0,x0); FMA2(A0[1],s0,x1); FMA2(A0[2],s0,x2);
            FMA2(A0[3],s0,x3); FMA2(A0[4],s0,x4);
            FMA2(A1[0],s1,x0); FMA2(A1[1],s1,x1); FMA2(A1[2],s1,x2);
            FMA2(A1[3],s1,x3); FMA2(A1[4],s1,x4);
        }
    }

    // ---- staged quarter-reduce in the union (region safe after sync1) ----
    const int r0 = ((p * 2 + 0) * IN_CH) * 32 + l;   // jh=0 slot base
    const int r1 = ((p * 2 + 1) * IN_CH) * 32 + l;   // jh=1 slot base
    __syncthreads();                                  // sync1: Spk/Xp reads done
    if (q == 1) {
        #pragma unroll
        for (int c = 0; c < IN_CH; c++) { set0[r0 + c*32] = A0[c]; set0[r1 + c*32] = A1[c]; }
    } else if (q == 3) {
        #pragma unroll
        for (int c = 0; c < IN_CH; c++) { set1[r0 + c*32] = A0[c]; set1[r1 + c*32] = A1[c]; }
    }
    __syncthreads();                                  // sync2
    if (q == 0) {
        #pragma unroll
        for (int c = 0; c < IN_CH; c++) { ADD2(A0[c], set0[r0 + c*32]); ADD2(A1[c], set0[r1 + c*32]); }
    } else if (q == 2) {
        #pragma unroll
        for (int c = 0; c < IN_CH; c++) { ADD2(A0[c], set1[r0 + c*32]); ADD2(A1[c], set1[r1 + c*32]); }
    }
    __syncthreads();                                  // sync3
    if (q == 2) {
        #pragma unroll
        for (int c = 0; c < IN_CH; c++) { set0[r0 + c*32] = A0[c]; set0[r1 + c*32] = A1[c]; }
    }
    __syncthreads();                                  // sync4
    if (q == 0) {
        #pragma unroll
        for (int c = 0; c < IN_CH; c++) { ADD2(A0[c], set0[r0 + c*32]); ADD2(A1[c], set0[r1 + c*32]); }
        // write Y: Ysh[g][c][j]; pads j=62,63 carry true zeros (S pad cols = 0)
        float lo, hi;
        #pragma unroll
        for (int c = 0; c < IN_CH; c++) {
            UNPK2(lo, hi, A0[c]);
            Ysh[(2*p)   * 320 + c * 64 + l] = lo;
            Ysh[(2*p+1) * 320 + c * 64 + l] = hi;
            UNPK2(lo, hi, A1[c]);
            Ysh[(2*p)   * 320 + c * 64 + l + 32] = lo;
            Ysh[(2*p+1) * 320 + c * 64 + l + 32] = hi;
        }
    }
    __syncthreads();                                  // sync5: Ysh ready

    // ---- phase B: 2 warps per graph, lane = hidden unit o ----
    const int o    = tid & 31;
    const int g    = w >> 1;             // 0..7
    const int half = w & 1;
    const float bo = bsh[o];
    u64 wd0,wd1,wd2,wd3,wd4,bd;
    PACK2(wd0, Wsh[o][0]); PACK2(wd1, Wsh[o][1]); PACK2(wd2, Wsh[o][2]);
    PACK2(wd3, Wsh[o][3]); PACK2(wd4, Wsh[o][4]);
    PACK2(bd, bo);
    const float f0 = Fsh[0][o], f1 = Fsh[1][o], f2 = Fsh[2][o];

    {
        const unsigned yb = (unsigned)__cvta_generic_to_shared(&Ysh[g * 320])
                            + half * 128;             // j offset 32
        float ph = 0.f;
        #pragma unroll 4
        for (int k = 0; k < 16; k++) {                // 16 j-pairs per warp
            u64 y0,y1,y2,y3,y4;
            const unsigned a = yb + k * 8;
            asm("ld.shared.u64 %0, [%1];"      : "=l"(y0) : "r"(a));
            asm("ld.shared.u64 %0, [%1+256];"  : "=l"(y1) : "r"(a));
            asm("ld.shared.u64 %0, [%1+512];"  : "=l"(y2) : "r"(a));
            asm("ld.shared.u64 %0, [%1+768];"  : "=l"(y3) : "r"(a));
            asm("ld.shared.u64 %0, [%1+1024];" : "=l"(y4) : "r"(a));
            u64 v = bd;
            FMA2(v, wd0, y0); FMA2(v, wd1, y1); FMA2(v, wd2, y2);
            FMA2(v, wd3, y3); FMA2(v, wd4, y4);
            float lo, hi; UNPK2(lo, hi, v);
            ph += fmaxf(lo, 0.f);
            ph += fmaxf(hi, 0.f);
        }
        if (half == 1) ph -= 2.f * fmaxf(bo, 0.f);    // remove j=62,63 pad bias
        float s0 = f0 * ph, s1 = f1 * ph, s2 = f2 * ph;
        #pragma unroll
        for (int off = 16; off > 0; off >>= 1) {
            s0 += __shfl_down_sync(0xffffffffu, s0, off);
            s1 += __shfl_down_sync(0xffffffffu, s1, off);
            s2 += __shfl_down_sync(0xffffffffu, s2, off);
        }
        if (o == 0) {
            red[g][half][0] = s0;
            red[g][half][1] = s1;
            red[g][half][2] = s2;
        }
    }
    __syncthreads();

    if (tid < GPB * N_CLS) {
        const int gg = tid / N_CLS, c = tid % N_CLS;
        if (g0 + gg < B)
            out[(size_t)(g0 + gg) * N_CLS + c] =
                red[gg][0][c] + red[gg][1][c] + fcb[c];
    }
}

// ---------------------------------------------------------------------------
extern "C" void kernel_launch(void* const* d_in, const int* in_sizes, int n_in,
                              void* d_out, int out_size) {
    const float* x        = (const float*)d_in[0];
    const float* adj_tril = (const float*)d_in[1];
    const float* lin_w    = (const float*)d_in[2];
    const float* lin_b    = (const float*)d_in[3];
    const float* fc_w     = (const float*)d_in[4];
    const float* fc_b     = (const float*)d_in[5];
    // d_in[6] edge_index / d_in[7] batch_idx are structurally redundant.

    const int B = in_sizes[0] / (N_ELEC * IN_CH);

    rgnn_setup_kernel<<<N_ELEC, 128>>>(adj_tril);

    const int grid = (B + GPB - 1) / GPB;
    rgnn_main_kernel<<<grid, NTHR>>>(x, lin_w, lin_b, fc_w, fc_b,
                                     (float*)d_out, B);
}

// round 8
// speedup vs baseline: 1.2670x; 1.0860x over previous
#include <cuda_runtime.h>

#define N_ELEC 62
#define IN_CH  5
#define HID    32
#define N_CLS  3
#define GPB    16          // graphs per block = 8 f32x2 pairs
#define NPAIRS 8
#define NTHR   512

// S = M^2 stored PAIR-INTERLEAVED: g_S[i*64 + 2*l + h] = S[i][l + 32*h]
__device__ float g_S[N_ELEC * 64];

typedef unsigned long long u64;

#define FMA2(acc, a, b) \
    asm("fma.rn.f32x2 %0, %1, %2, %0;" : "+l"(acc) : "l"(a), "l"(b))
#define ADD2(acc, v) \
    asm("add.rn.f32x2 %0, %0, %1;" : "+l"(acc) : "l"(v))
#define PACK2(d, s) \
    asm("mov.b64 %0, {%1, %1};" : "=l"(d) : "f"(s))
#define MERGE2(d, lo, hi) \
    asm("mov.b64 %0, {%1, %2};" : "=l"(d) : "f"(lo), "f"(hi))
#define UNPK2(lo, hi, v) \
    asm("mov.b64 {%0, %1}, %2;" : "=f"(lo), "=f"(hi) : "l"(v))

// ---------------------------------------------------------------------------
// Setup: grid = 62 blocks, block i computes row i of S = M @ M, interleaved.
// Triggers programmatic launch completion at entry so the main kernel's
// prologue (X/weights staging) overlaps with this kernel's execution.
// ---------------------------------------------------------------------------
__global__ __launch_bounds__(128) void rgnn_setup_kernel(
    const float* __restrict__ adj_tril)
{
    cudaTriggerProgrammaticLaunchCompletion();

    __shared__ float A[N_ELEC * 64];
    __shared__ float dinv[N_ELEC];
    __shared__ float t[N_ELEC];
    const int tid = threadIdx.x;
    const int i   = blockIdx.x;

    for (int idx = tid; idx < N_ELEC * N_ELEC; idx += 128) {
        int r = idx / N_ELEC, c = idx % N_ELEC;
        int a = r > c ? r : c;
        int b = r > c ? c : r;
        A[r * 64 + c] = adj_tril[a * (a + 1) / 2 + b];
    }
    __syncthreads();

    if (tid < N_ELEC) {
        float d = 0.f;
        #pragma unroll 2
        for (int c = 0; c < N_ELEC; c++) d += fabsf(A[tid * 64 + c]);
        dinv[tid] = (d > 0.f) ? rsqrtf(d) : 0.f;
    }
    __syncthreads();

    if (tid < N_ELEC) {
        float dk = dinv[tid];
        t[tid] = dinv[i] * dk * dk * A[i * 64 + tid];
    }
    __syncthreads();

    if (tid < 64) {
        const int j = tid;
        float s = 0.f;
        if (j < N_ELEC) {
            #pragma unroll 2
            for (int k = 0; k < N_ELEC; k++)
                s = fmaf(t[k], A[k * 64 + j], s);
            s *= dinv[j];
        }
        // pair-interleaved: slot = 2*(j&31) + (j>>5); pads j=62,63 -> 0
        g_S[i * 64 + ((j & 31) << 1) + (j >> 5)] = s;
    }
}

// ---------------------------------------------------------------------------
// Main kernel: 16 graphs/block, 16 warps. Phase A warp = (pair, i-half);
// phase B warp = (pair, j-half). Y stays packed (even,odd) u64 throughout.
// ---------------------------------------------------------------------------
__global__ __launch_bounds__(NTHR) void rgnn_main_kernel(
    const float* __restrict__ x, const float* __restrict__ lin_w,
    const float* __restrict__ lin_b, const float* __restrict__ fc_w,
    const float* __restrict__ fc_b, float* __restrict__ out, int B)
{
    // Union (40960 B):
    //  phase A : Spk [62*64]f @0 (15872B) | Xp [8][62][6]u64 @15872 (23808B)
    //  reduce  : set [8][2][5][32]u64 @0 (20480B)      (written after sync1)
    //  phase B : Ypk [8][5][64]u64 @20480 (20480B)     (written after sync2)
    __shared__ __align__(16) float uni[10240];
    float* Spk = uni;
    u64*   Xp  = (u64*)(uni + 3968);
    u64*   set = (u64*)uni;
    u64*   Ypk = (u64*)(uni + 5120);
    __shared__ float Wsh[HID][IN_CH];
    __shared__ float bsh[HID];
    __shared__ float Fsh[N_CLS][HID];
    __shared__ float fcb[N_CLS];
    __shared__ float red[NPAIRS][2][6];   // [pair][jhalf][par*3+cls]

    const int tid = threadIdx.x;
    const int g0  = blockIdx.x * GPB;

    // ---- prologue (independent of g_S; overlaps setup via PDL) ----
    if (tid < HID * IN_CH + HID + N_CLS * HID + N_CLS) {
        const int idx = tid;
        if (idx < 160)      ((float*)Wsh)[idx] = lin_w[idx];
        else if (idx < 192) bsh[idx - 160] = lin_b[idx - 160];
        else if (idx < 288) ((float*)Fsh)[idx - 192] = fc_w[idx - 192];
        else                fcb[idx - 288] = fc_b[idx - 288];
    }
    // X staging: thread t<496 -> (pair u, node i); no per-element div/mod.
    if (tid < 496) {
        const int u  = tid / 62;
        const int i  = tid - u * 62;
        const int gA = g0 + 2 * u;
        const float* se = x + (size_t)gA * (N_ELEC * IN_CH) + i * IN_CH;
        float e0=0,e1=0,e2=0,e3=0,e4=0, o0=0,o1=0,o2=0,o3=0,o4=0;
        if (gA < B) {
            e0 = se[0]; e1 = se[1]; e2 = se[2]; e3 = se[3]; e4 = se[4];
            if (gA + 1 < B) {
                const float* so = se + N_ELEC * IN_CH;
                o0 = so[0]; o1 = so[1]; o2 = so[2]; o3 = so[3]; o4 = so[4];
            }
        }
        u64 q0,q1,q2,q3,q4;
        MERGE2(q0,e0,o0); MERGE2(q1,e1,o1); MERGE2(q2,e2,o2);
        MERGE2(q3,e3,o3); MERGE2(q4,e4,o4);
        u64* xw = &Xp[u * 372 + i * 6];
        xw[0]=q0; xw[1]=q1; xw[2]=q2; xw[3]=q3; xw[4]=q4;
    }

    // ---- wait for setup's g_S, then stage S ----
    cudaGridDependencySynchronize();
    {
        const float4* gs4 = (const float4*)g_S;
        float4* ss4 = (float4*)Spk;
        for (int idx = tid; idx < N_ELEC * 64 / 4; idx += NTHR)
            ss4[idx] = gs4[idx];
    }
    __syncthreads();

    // ---- phase A: warp = (pair p, i-half h); thread covers j = l, l+32 ----
    const int l = tid & 31;
    const int w = tid >> 5;              // 0..15
    const int p = w & 7;                 // pair -> graphs 2p, 2p+1
    const int h = w >> 3;                // i-half: [0,31) or [31,62)
    const int ibeg = h * 31;

    u64 A0[IN_CH], A1[IN_CH];
    #pragma unroll
    for (int c = 0; c < IN_CH; c++) { A0[c] = 0ull; A1[c] = 0ull; }

    {
        const unsigned sb = (unsigned)__cvta_generic_to_shared(Spk)
                            + l * 8 + ibeg * 256;
        const unsigned xb = (unsigned)__cvta_generic_to_shared(Xp)
                            + p * 2976 + ibeg * 48;
        #pragma unroll 4
        for (int ii = 0; ii < 31; ii++) {
            u64 spk;
            asm("ld.shared.u64 %0, [%1];" : "=l"(spk) : "r"(sb + ii * 256));
            float slo, shi; UNPK2(slo, shi, spk);
            u64 s0, s1; PACK2(s0, slo); PACK2(s1, shi);
            u64 x0,x1,x2,x3,x4;
            const unsigned a = xb + ii * 48;
            asm("ld.shared.v2.u64 {%0,%1}, [%2];"    : "=l"(x0), "=l"(x1) : "r"(a));
            asm("ld.shared.v2.u64 {%0,%1}, [%2+16];" : "=l"(x2), "=l"(x3) : "r"(a));
            asm("ld.shared.u64 %0, [%1+32];"         : "=l"(x4)           : "r"(a));
            FMA2(A0[0],s0,x0); FMA2(A0[1],s0,x1); FMA2(A0[2],s0,x2);
            FMA2(A0[3],s0,x3); FMA2(A0[4],s0,x4);
            FMA2(A1[0],s1,x0); FMA2(A1[1],s1,x1); FMA2(A1[2],s1,x2);
            FMA2(A1[3],s1,x3); FMA2(A1[4],s1,x4);
        }
    }

    // ---- single-stage half-reduce; write Ypk packed ----
    __syncthreads();                      // sync1: Spk/Xp reads retired
    if (h == 1) {
        #pragma unroll
        for (int c = 0; c < IN_CH; c++) {
            set[((p * 2 + 0) * IN_CH + c) * 32 + l] = A0[c];
            set[((p * 2 + 1) * IN_CH + c) * 32 + l] = A1[c];
        }
    }
    __syncthreads();                      // sync2
    if (h == 0) {
        #pragma unroll
        for (int c = 0; c < IN_CH; c++) {
            ADD2(A0[c], set[((p * 2 + 0) * IN_CH + c) * 32 + l]);
            ADD2(A1[c], set[((p * 2 + 1) * IN_CH + c) * 32 + l]);
            Ypk[(p * IN_CH + c) * 64 + l]      = A0[c];
            Ypk[(p * IN_CH + c) * 64 + l + 32] = A1[c];
        }
    }
    __syncthreads();                      // sync3: Ypk ready

    // ---- phase B: warp = (pair, j-half); lane = hidden unit o ----
    const int o  = l;
    const int pB = w >> 1;
    const int jh = w & 1;                 // j in [jh*31, jh*31+31)
    u64 wd0,wd1,wd2,wd3,wd4,bd;
    PACK2(wd0, Wsh[o][0]); PACK2(wd1, Wsh[o][1]); PACK2(wd2, Wsh[o][2]);
    PACK2(wd3, Wsh[o][3]); PACK2(wd4, Wsh[o][4]);
    PACK2(bd, bsh[o]);
    const float f0 = Fsh[0][o], f1 = Fsh[1][o], f2 = Fsh[2][o];

    {
        const unsigned yb = (unsigned)__cvta_generic_to_shared(Ypk)
                            + pB * 2560 + jh * 248;   // 31 j's * 8B
        float ph0 = 0.f, ph1 = 0.f;
        #pragma unroll 4
        for (int k = 0; k < 31; k++) {
            u64 y0,y1,y2,y3,y4;
            const unsigned a = yb + k * 8;
            asm("ld.shared.u64 %0, [%1];"       : "=l"(y0) : "r"(a));
            asm("ld.shared.u64 %0, [%1+512];"   : "=l"(y1) : "r"(a));
            asm("ld.shared.u64 %0, [%1+1024];"  : "=l"(y2) : "r"(a));
            asm("ld.shared.u64 %0, [%1+1536];"  : "=l"(y3) : "r"(a));
            asm("ld.shared.u64 %0, [%1+2048];"  : "=l"(y4) : "r"(a));
            u64 v = bd;
            FMA2(v, wd0, y0); FMA2(v, wd1, y1); FMA2(v, wd2, y2);
            FMA2(v, wd3, y3); FMA2(v, wd4, y4);
            float lo, hi; UNPK2(lo, hi, v);
            ph0 += fmaxf(lo, 0.f);               // graph 2*pB
            ph1 += fmaxf(hi, 0.f);               // graph 2*pB+1
        }
        float s0 = f0 * ph0, s1 = f1 * ph0, s2 = f2 * ph0;
        float t0 = f0 * ph1, t1 = f1 * ph1, t2 = f2 * ph1;
        #pragma unroll
        for (int off = 16; off > 0; off >>= 1) {
            s0 += __shfl_down_sync(0xffffffffu, s0, off);
            s1 += __shfl_down_sync(0xffffffffu, s1, off);
            s2 += __shfl_down_sync(0xffffffffu, s2, off);
            t0 += __shfl_down_sync(0xffffffffu, t0, off);
            t1 += __shfl_down_sync(0xffffffffu, t1, off);
            t2 += __shfl_down_sync(0xffffffffu, t2, off);
        }
        if (o == 0) {
            red[pB][jh][0] = s0; red[pB][jh][1] = s1; red[pB][jh][2] = s2;
            red[pB][jh][3] = t0; red[pB][jh][4] = t1; red[pB][jh][5] = t2;
        }
    }
    __syncthreads();

    if (tid < GPB * N_CLS) {
        const int gg = tid / N_CLS, c = tid % N_CLS;
        const int pp = gg >> 1, par = gg & 1;
        if (g0 + gg < B)
            out[(size_t)(g0 + gg) * N_CLS + c] =
                red[pp][0][par * 3 + c] + red[pp][1][par * 3 + c] + fcb[c];
    }
}

// ---------------------------------------------------------------------------
extern "C" void kernel_launch(void* const* d_in, const int* in_sizes, int n_in,
                              void* d_out, int out_size) {
    const float* x        = (const float*)d_in[0];
    const float* adj_tril = (const float*)d_in[1];
    const float* lin_w    = (const float*)d_in[2];
    const float* lin_b    = (const float*)d_in[3];
    const float* fc_w     = (const float*)d_in[4];
    const float* fc_b     = (const float*)d_in[5];
    // d_in[6] edge_index / d_in[7] batch_idx are structurally redundant.

    const int B = in_sizes[0] / (N_ELEC * IN_CH);

    rgnn_setup_kernel<<<N_ELEC, 128>>>(adj_tril);

    // Main kernel with programmatic dependent launch: prologue overlaps setup;
    // correctness guaranteed by cudaGridDependencySynchronize before g_S reads.
    const int grid = (B + GPB - 1) / GPB;
    cudaLaunchConfig_t cfg = {};
    cfg.gridDim  = dim3((unsigned)grid);
    cfg.blockDim = dim3(NTHR);
    cfg.dynamicSmemBytes = 0;
    cfg.stream = 0;
    cudaLaunchAttribute at[1];
    at[0].id = cudaLaunchAttributeProgrammaticStreamSerialization;
    at[0].val.programmaticStreamSerializationAllowed = 1;
    cfg.attrs = at;
    cfg.numAttrs = 1;
    cudaLaunchKernelEx(&cfg, rgnn_main_kernel,
                       x, lin_w, lin_b, fc_w, fc_b, (float*)d_out, B);
}

// round 9
// speedup vs baseline: 1.2689x; 1.0015x over previous
#include <cuda_runtime.h>

#define N_ELEC 62
#define IN_CH  5
#define HID    32
#define N_CLS  3
#define GPB    16          // graphs per block = 8 f32x2 pairs
#define NPAIRS 8
#define NTHR   512

// S = M^2 stored PAIR-INTERLEAVED: g_S[i*64 + 2*l + h] = S[i][l + 32*h]
__device__ float g_S[N_ELEC * 64];

typedef unsigned long long u64;

#define FMA2(acc, a, b) \
    asm("fma.rn.f32x2 %0, %1, %2, %0;" : "+l"(acc) : "l"(a), "l"(b))
#define ADD2(acc, v) \
    asm("add.rn.f32x2 %0, %0, %1;" : "+l"(acc) : "l"(v))
#define PACK2(d, s) \
    asm("mov.b64 %0, {%1, %1};" : "=l"(d) : "f"(s))
#define MERGE2(d, lo, hi) \
    asm("mov.b64 %0, {%1, %2};" : "=l"(d) : "f"(lo), "f"(hi))
#define UNPK2(lo, hi, v) \
    asm("mov.b64 {%0, %1}, %2;" : "=f"(lo), "=f"(hi) : "l"(v))

// ---------------------------------------------------------------------------
// Setup: grid = 62 blocks, block i computes row i of S = M @ M, interleaved.
// Triggers programmatic launch completion at entry so the main kernel's
// prologue (X/weights staging) overlaps with this kernel's execution.
// ---------------------------------------------------------------------------
__global__ __launch_bounds__(128) void rgnn_setup_kernel(
    const float* __restrict__ adj_tril)
{
    cudaTriggerProgrammaticLaunchCompletion();

    __shared__ float A[N_ELEC * 64];
    __shared__ float dinv[N_ELEC];
    __shared__ float t[N_ELEC];
    const int tid = threadIdx.x;
    const int i   = blockIdx.x;

    for (int idx = tid; idx < N_ELEC * N_ELEC; idx += 128) {
        int r = idx / N_ELEC, c = idx % N_ELEC;
        int a = r > c ? r : c;
        int b = r > c ? c : r;
        A[r * 64 + c] = adj_tril[a * (a + 1) / 2 + b];
    }
    __syncthreads();

    if (tid < N_ELEC) {
        float d = 0.f;
        #pragma unroll 2
        for (int c = 0; c < N_ELEC; c++) d += fabsf(A[tid * 64 + c]);
        dinv[tid] = (d > 0.f) ? rsqrtf(d) : 0.f;
    }
    __syncthreads();

    if (tid < N_ELEC) {
        float dk = dinv[tid];
        t[tid] = dinv[i] * dk * dk * A[i * 64 + tid];
    }
    __syncthreads();

    if (tid < 64) {
        const int j = tid;
        float s = 0.f;
        if (j < N_ELEC) {
            #pragma unroll 2
            for (int k = 0; k < N_ELEC; k++)
                s = fmaf(t[k], A[k * 64 + j], s);
            s *= dinv[j];
        }
        // pair-interleaved: slot = 2*(j&31) + (j>>5); pads j=62,63 -> 0
        g_S[i * 64 + ((j & 31) << 1) + (j >> 5)] = s;
    }
}

// ---------------------------------------------------------------------------
// Main kernel: 16 graphs/block, 16 warps. Phase A warp = (pair, i-half);
// phase B warp = (pair, j-half). Y stays packed (even,odd) u64 throughout.
// ---------------------------------------------------------------------------
__global__ __launch_bounds__(NTHR) void rgnn_main_kernel(
    const float* __restrict__ x, const float* __restrict__ lin_w,
    const float* __restrict__ lin_b, const float* __restrict__ fc_w,
    const float* __restrict__ fc_b, float* __restrict__ out, int B)
{
    // Union (40960 B):
    //  phase A : Spk [62*64]f @0 (15872B) | Xp [8][62][6]u64 @15872 (23808B)
    //  reduce  : set [8][2][5][32]u64 @0 (20480B)      (written after sync1)
    //  phase B : Ypk [8][5][64]u64 @20480 (20480B)     (written after sync2)
    __shared__ __align__(16) float uni[10240];
    float* Spk = uni;
    u64*   Xp  = (u64*)(uni + 3968);
    u64*   set = (u64*)uni;
    u64*   Ypk = (u64*)(uni + 5120);
    __shared__ float Wsh[HID][IN_CH];
    __shared__ float bsh[HID];
    __shared__ float Fsh[N_CLS][HID];
    __shared__ float fcb[N_CLS];
    __shared__ float red[NPAIRS][2][6];   // [pair][jhalf][par*3+cls]

    const int tid = threadIdx.x;
    const int g0  = blockIdx.x * GPB;

    // ---- prologue (independent of g_S; overlaps setup via PDL) ----
    if (tid < HID * IN_CH + HID + N_CLS * HID + N_CLS) {
        const int idx = tid;
        if (idx < 160)      ((float*)Wsh)[idx] = lin_w[idx];
        else if (idx < 192) bsh[idx - 160] = lin_b[idx - 160];
        else if (idx < 288) ((float*)Fsh)[idx - 192] = fc_w[idx - 192];
        else                fcb[idx - 288] = fc_b[idx - 288];
    }
    // X staging: thread t<496 -> (pair u, node i); no per-element div/mod.
    if (tid < 496) {
        const int u  = tid / 62;
        const int i  = tid - u * 62;
        const int gA = g0 + 2 * u;
        const float* se = x + (size_t)gA * (N_ELEC * IN_CH) + i * IN_CH;
        float e0=0,e1=0,e2=0,e3=0,e4=0, o0=0,o1=0,o2=0,o3=0,o4=0;
        if (gA < B) {
            e0 = se[0]; e1 = se[1]; e2 = se[2]; e3 = se[3]; e4 = se[4];
            if (gA + 1 < B) {
                const float* so = se + N_ELEC * IN_CH;
                o0 = so[0]; o1 = so[1]; o2 = so[2]; o3 = so[3]; o4 = so[4];
            }
        }
        u64 q0,q1,q2,q3,q4;
        MERGE2(q0,e0,o0); MERGE2(q1,e1,o1); MERGE2(q2,e2,o2);
        MERGE2(q3,e3,o3); MERGE2(q4,e4,o4);
        u64* xw = &Xp[u * 372 + i * 6];
        xw[0]=q0; xw[1]=q1; xw[2]=q2; xw[3]=q3; xw[4]=q4;
    }

    // ---- wait for setup's g_S, then stage S ----
    cudaGridDependencySynchronize();
    {
        const float4* gs4 = (const float4*)g_S;
        float4* ss4 = (float4*)Spk;
        for (int idx = tid; idx < N_ELEC * 64 / 4; idx += NTHR)
            ss4[idx] = gs4[idx];
    }
    __syncthreads();

    // ---- phase A: warp = (pair p, i-half h); thread covers j = l, l+32 ----
    const int l = tid & 31;
    const int w = tid >> 5;              // 0..15
    const int p = w & 7;                 // pair -> graphs 2p, 2p+1
    const int h = w >> 3;                // i-half: [0,31) or [31,62)
    const int ibeg = h * 31;

    u64 A0[IN_CH], A1[IN_CH];
    #pragma unroll
    for (int c = 0; c < IN_CH; c++) { A0[c] = 0ull; A1[c] = 0ull; }

    {
        const unsigned sb = (unsigned)__cvta_generic_to_shared(Spk)
                            + l * 8 + ibeg * 256;
        const unsigned xb = (unsigned)__cvta_generic_to_shared(Xp)
                            + p * 2976 + ibeg * 48;
        #pragma unroll 4
        for (int ii = 0; ii < 31; ii++) {
            u64 spk;
            asm("ld.shared.u64 %0, [%1];" : "=l"(spk) : "r"(sb + ii * 256));
            float slo, shi; UNPK2(slo, shi, spk);
            u64 s0, s1; PACK2(s0, slo); PACK2(s1, shi);
            u64 x0,x1,x2,x3,x4;
            const unsigned a = xb + ii * 48;
            asm("ld.shared.v2.u64 {%0,%1}, [%2];"    : "=l"(x0), "=l"(x1) : "r"(a));
            asm("ld.shared.v2.u64 {%0,%1}, [%2+16];" : "=l"(x2), "=l"(x3) : "r"(a));
            asm("ld.shared.u64 %0, [%1+32];"         : "=l"(x4)           : "r"(a));
            FMA2(A0[0],s0,x0); FMA2(A0[1],s0,x1); FMA2(A0[2],s0,x2);
            FMA2(A0[3],s0,x3); FMA2(A0[4],s0,x4);
            FMA2(A1[0],s1,x0); FMA2(A1[1],s1,x1); FMA2(A1[2],s1,x2);
            FMA2(A1[3],s1,x3); FMA2(A1[4],s1,x4);
        }
    }

    // ---- single-stage half-reduce; write Ypk packed ----
    __syncthreads();                      // sync1: Spk/Xp reads retired
    if (h == 1) {
        #pragma unroll
        for (int c = 0; c < IN_CH; c++) {
            set[((p * 2 + 0) * IN_CH + c) * 32 + l] = A0[c];
            set[((p * 2 + 1) * IN_CH + c) * 32 + l] = A1[c];
        }
    }
    __syncthreads();                      // sync2
    if (h == 0) {
        #pragma unroll
        for (int c = 0; c < IN_CH; c++) {
            ADD2(A0[c], set[((p * 2 + 0) * IN_CH + c) * 32 + l]);
            ADD2(A1[c], set[((p * 2 + 1) * IN_CH + c) * 32 + l]);
            Ypk[(p * IN_CH + c) * 64 + l]      = A0[c];
            Ypk[(p * IN_CH + c) * 64 + l + 32] = A1[c];
        }
    }
    __syncthreads();                      // sync3: Ypk ready

    // ---- phase B: warp = (pair, j-half); lane = hidden unit o ----
    const int o  = l;
    const int pB = w >> 1;
    const int jh = w & 1;                 // j in [jh*31, jh*31+31)
    u64 wd0,wd1,wd2,wd3,wd4,bd;
    PACK2(wd0, Wsh[o][0]); PACK2(wd1, Wsh[o][1]); PACK2(wd2, Wsh[o][2]);
    PACK2(wd3, Wsh[o][3]); PACK2(wd4, Wsh[o][4]);
    PACK2(bd, bsh[o]);
    const float f0 = Fsh[0][o], f1 = Fsh[1][o], f2 = Fsh[2][o];

    {
        const unsigned yb = (unsigned)__cvta_generic_to_shared(Ypk)
                            + pB * 2560 + jh * 248;   // 31 j's * 8B
        float ph0 = 0.f, ph1 = 0.f;
        #pragma unroll 4
        for (int k = 0; k < 31; k++) {
            u64 y0,y1,y2,y3,y4;
            const unsigned a = yb + k * 8;
            asm("ld.shared.u64 %0, [%1];"       : "=l"(y0) : "r"(a));
            asm("ld.shared.u64 %0, [%1+512];"   : "=l"(y1) : "r"(a));
            asm("ld.shared.u64 %0, [%1+1024];"  : "=l"(y2) : "r"(a));
            asm("ld.shared.u64 %0, [%1+1536];"  : "=l"(y3) : "r"(a));
            asm("ld.shared.u64 %0, [%1+2048];"  : "=l"(y4) : "r"(a));
            u64 v = bd;
            FMA2(v, wd0, y0); FMA2(v, wd1, y1); FMA2(v, wd2, y2);
            FMA2(v, wd3, y3); FMA2(v, wd4, y4);
            float lo, hi; UNPK2(lo, hi, v);
            ph0 += fmaxf(lo, 0.f);               // graph 2*pB
            ph1 += fmaxf(hi, 0.f);               // graph 2*pB+1
        }
        float s0 = f0 * ph0, s1 = f1 * ph0, s2 = f2 * ph0;
        float t0 = f0 * ph1, t1 = f1 * ph1, t2 = f2 * ph1;
        #pragma unroll
        for (int off = 16; off > 0; off >>= 1) {
            s0 += __shfl_down_sync(0xffffffffu, s0, off);
            s1 += __shfl_down_sync(0xffffffffu, s1, off);
            s2 += __shfl_down_sync(0xffffffffu, s2, off);
            t0 += __shfl_down_sync(0xffffffffu, t0, off);
            t1 += __shfl_down_sync(0xffffffffu, t1, off);
            t2 += __shfl_down_sync(0xffffffffu, t2, off);
        }
        if (o == 0) {
            red[pB][jh][0] = s0; red[pB][jh][1] = s1; red[pB][jh][2] = s2;
            red[pB][jh][3] = t0; red[pB][jh][4] = t1; red[pB][jh][5] = t2;
        }
    }
    __syncthreads();

    if (tid < GPB * N_CLS) {
        const int gg = tid / N_CLS, c = tid % N_CLS;
        const int pp = gg >> 1, par = gg & 1;
        if (g0 + gg < B)
            out[(size_t)(g0 + gg) * N_CLS + c] =
                red[pp][0][par * 3 + c] + red[pp][1][par * 3 + c] + fcb[c];
    }
}

// ---------------------------------------------------------------------------
extern "C" void kernel_launch(void* const* d_in, const int* in_sizes, int n_in,
                              void* d_out, int out_size) {
    const float* x        = (const float*)d_in[0];
    const float* adj_tril = (const float*)d_in[1];
    const float* lin_w    = (const float*)d_in[2];
    const float* lin_b    = (const float*)d_in[3];
    const float* fc_w     = (const float*)d_in[4];
    const float* fc_b     = (const float*)d_in[5];
    // d_in[6] edge_index / d_in[7] batch_idx are structurally redundant.

    const int B = in_sizes[0] / (N_ELEC * IN_CH);

    rgnn_setup_kernel<<<N_ELEC, 128>>>(adj_tril);

    // Main kernel with programmatic dependent launch: prologue overlaps setup;
    // correctness guaranteed by cudaGridDependencySynchronize before g_S reads.
    const int grid = (B + GPB - 1) / GPB;
    cudaLaunchConfig_t cfg = {};
    cfg.gridDim  = dim3((unsigned)grid);
    cfg.blockDim = dim3(NTHR);
    cfg.dynamicSmemBytes = 0;
    cfg.stream = 0;
    cudaLaunchAttribute at[1];
    at[0].id = cudaLaunchAttributeProgrammaticStreamSerialization;
    at[0].val.programmaticStreamSerializationAllowed = 1;
    cfg.attrs = at;
    cfg.numAttrs = 1;
    cudaLaunchKernelEx(&cfg, rgnn_main_kernel,
                       x, lin_w, lin_b, fc_w, fc_b, (float*)d_out, B);
}